// round 13
// baseline (speedup 1.0000x reference)
#include <cuda_runtime.h>
#include <cstdint>

// Problem constants
#define SN 256        // batch == seq_len
#define EE 1024       // embedding dim
#define HH 10         // hidden dim
#define NG 40         // 4 gates * H
#define TT 50         // tagset size
#define NP (SN*SN)    // 65536 rows (t,b)
#define WG_STRIDE 10340  // (E+H)*H per gate

// Phase A tiling (mma.sync m16n8k8 tf32)
#define BK 32         // k chunk
#define MT 128        // rows per tile
#define ATHREADS 128
#define NCH (EE/BK)   // 32 chunks
#define AST 36        // padded row stride (floats) -> conflict-free fragment loads
#define A_STAGE_F (MT*AST)   // 4608 floats
#define B_STAGE_F (NG*AST)   // 1440 floats

// smem layout (bytes)
#define SM_STOK 0
#define SM_A    1024
#define SM_B    (SM_A + 2*A_STAGE_F*4)      // 37888
#define SM_TOT  (SM_B + 2*B_STAGE_F*4)      // 49408

// A/B fusion: A = blocks 0..127 (4 t-ordered tiles each), B = blocks 128..383
#define NA_BLK 128
#define NQ 4               // t-quarters (64 t each, 128 tiles each)
#define TILES_PER_Q 128

// Scratch (no allocations allowed -> device globals)
__device__ float g_base[(size_t)NP * NG];   // x@Wx + bg + theta
__device__ float g_hx[(size_t)NP * HH];     // hx outputs of the scan
__device__ __align__(16) float g_Bt[NCH * NG * BK];  // B transposed per chunk, tf32-rounded
__device__ int g_qcnt[NQ];                  // per-quarter completed-tile counters

// ---------- helpers ----------
__device__ __forceinline__ void cp16(uint32_t dst, const void* src) {
    asm volatile("cp.async.cg.shared.global [%0], [%1], 16;" :: "r"(dst), "l"(src) : "memory");
}
__device__ __forceinline__ void hmma_tf32(float* d, uint32_t a0, uint32_t a1, uint32_t a2, uint32_t a3,
                                          uint32_t b0, uint32_t b1) {
    asm volatile(
        "mma.sync.aligned.m16n8k8.row.col.f32.tf32.tf32.f32 "
        "{%0,%1,%2,%3}, {%4,%5,%6,%7}, {%8,%9}, {%0,%1,%2,%3};"
        : "+f"(d[0]), "+f"(d[1]), "+f"(d[2]), "+f"(d[3])
        : "r"(a0), "r"(a1), "r"(a2), "r"(a3), "r"(b0), "r"(b1));
}
__device__ __forceinline__ float tanhapx(float x) {
    float y;
    asm("tanh.approx.f32 %0, %1;" : "=f"(y) : "f"(x));
    return y;
}

// =========================================================================
// zero the quarter counters (fresh every launch / graph replay)
// =========================================================================
__global__ void zeroQ_kernel() { if (threadIdx.x < NQ) g_qcnt[threadIdx.x] = 0; }

// =========================================================================
// B pre-transpose + tf32 round: g_Bt[ch][n][k]
// =========================================================================
__global__ __launch_bounds__(256) void prepB_kernel(const float* __restrict__ Wg)
{
    int idx = blockIdx.x * 256 + threadIdx.x;          // 0..40959
    if (idx >= NCH * NG * BK) return;
    int ch = idx / (NG * BK);
    int r  = idx % (NG * BK);
    int n  = r / BK, k = r % BK;
    float v = Wg[(n / HH) * WG_STRIDE + (ch * BK + k) * HH + (n % HH)];
    uint32_t u;
    asm("cvt.rna.tf32.f32 %0, %1;" : "=r"(u) : "f"(v));
    g_Bt[idx] = __uint_as_float(u);
}

// =========================================================================
// Fused A+B kernel.
// Blocks 0..127: phase A — gathered skinny GEMM on mma.sync tf32, each block
//   does 4 tiles in t order (tile = q*128 + blk), releasing g_qcnt[q].
// Blocks 128..383: phase B — one LSTM chain per warp (warp 0 of the block),
//   spin-gated on g_qcnt when the 4-step prefetch crosses a 64-t boundary.
// A never waits on B, so worst-case scheduling degrades to sequential A;B.
// =========================================================================
extern __shared__ char smem_raw[];

__global__ __launch_bounds__(128, 4) void phaseAB_kernel(
    const int* __restrict__ tok, const float* __restrict__ emb,
    const float* __restrict__ bg, const float* __restrict__ theta,
    const float* __restrict__ Wg)
{
    if (blockIdx.x < NA_BLK) {
        // ============================ A part ============================
        int*   stok = (int*)(smem_raw + SM_STOK);
        float* sA   = (float*)(smem_raw + SM_A);
        float* sB   = (float*)(smem_raw + SM_B);

        const int tid = threadIdx.x;
        const int wid  = tid >> 5, lane = tid & 31;
        const int g    = lane >> 2, t = lane & 3;
        const int w32  = wid * 32;

        const uint32_t sA_base = (uint32_t)__cvta_generic_to_shared(sA);
        const uint32_t sB_base = (uint32_t)__cvta_generic_to_shared(sB);

        for (int q = 0; q < NQ; q++) {
            const int tile = q * TILES_PER_Q + blockIdx.x;
            const int rowbase = tile * MT;

            if (tid < MT) stok[tid] = tok[rowbase + tid];
            __syncthreads();

            float acc[2][5][4];
#pragma unroll
            for (int m = 0; m < 2; m++)
#pragma unroll
                for (int n = 0; n < 5; n++)
#pragma unroll
                    for (int qq = 0; qq < 4; qq++) acc[m][n][qq] = 0.f;

            auto issue_chunk = [&](int ch) {
                const int s = ch & 1;
                const uint32_t abase = sA_base + (uint32_t)(s * A_STAGE_F * 4);
#pragma unroll
                for (int it = 0; it < 8; it++) {
                    int idx = it * ATHREADS + tid;
                    int row = idx >> 3, c = idx & 7;
                    cp16(abase + (uint32_t)(row * (AST * 4) + (c << 4)),
                         emb + (size_t)stok[row] * EE + ch * BK + (c << 2));
                }
                const uint32_t bbase = sB_base + (uint32_t)(s * B_STAGE_F * 4);
                const float* bsrc = g_Bt + ch * (NG * BK);
#pragma unroll
                for (int it = 0; it < 3; it++) {
                    int i = it * ATHREADS + tid;
                    if (i < NG * 8) {
                        int n = i >> 3, kq = i & 7;
                        cp16(bbase + (uint32_t)(n * (AST * 4) + (kq << 4)), bsrc + (i << 2));
                    }
                }
                asm volatile("cp.async.commit_group;" ::: "memory");
            };

            issue_chunk(0);

            for (int ch = 0; ch < NCH; ch++) {
                asm volatile("cp.async.wait_group 0;" ::: "memory");
                __syncthreads();
                if (ch + 1 < NCH) issue_chunk(ch + 1);

                const int s = ch & 1;
                const uint32_t* A = (const uint32_t*)(sA + s * A_STAGE_F);
                const uint32_t* B = (const uint32_t*)(sB + s * B_STAGE_F);
#pragma unroll
                for (int s4 = 0; s4 < 4; s4++) {
                    uint32_t b0[5], b1[5];
#pragma unroll
                    for (int n = 0; n < 5; n++) {
                        const uint32_t* bp = B + (n * 8 + g) * AST + s4 * 8 + t;
                        b0[n] = bp[0];
                        b1[n] = bp[4];
                    }
#pragma unroll
                    for (int m = 0; m < 2; m++) {
                        const uint32_t* ap = A + (w32 + m * 16 + g) * AST + s4 * 8 + t;
                        uint32_t a0 = ap[0];
                        uint32_t a2 = ap[4];
                        uint32_t a1 = ap[8 * AST];
                        uint32_t a3 = ap[8 * AST + 4];
#pragma unroll
                        for (int n = 0; n < 5; n++)
                            hmma_tf32(acc[m][n], a0, a1, a2, a3, b0[n], b1[n]);
                    }
                }
            }

            // epilogue: add bg + theta, store
            float cbx[5], cby[5];
#pragma unroll
            for (int n = 0; n < 5; n++) {
                int col = n * 8 + 2 * t;
                cbx[n] = bg[col] + theta[col];
                cby[n] = bg[col + 1] + theta[col + 1];
            }
#pragma unroll
            for (int m = 0; m < 2; m++) {
                int row0 = rowbase + w32 + m * 16 + g;
#pragma unroll
                for (int n = 0; n < 5; n++) {
                    int col = n * 8 + 2 * t;
                    *(float2*)(g_base + (size_t)row0 * NG + col) =
                        make_float2(acc[m][n][0] + cbx[n], acc[m][n][1] + cby[n]);
                    *(float2*)(g_base + (size_t)(row0 + 8) * NG + col) =
                        make_float2(acc[m][n][2] + cbx[n], acc[m][n][3] + cby[n]);
                }
            }

            __syncthreads();                 // all tile stores done block-wide
            if (tid == 0) {
                __threadfence();             // release
                atomicAdd(&g_qcnt[q], 1);
            }
        }
        return;
    }

    // ============================ B part ============================
    if (threadIdx.x >= 32) return;           // one warp per chain

    const int lane = threadIdx.x;
    const int grp  = lane >> 4;          // 0: f,i   1: g,o
    const int l    = lane & 15;
    const int b    = blockIdx.x - NA_BLK;
    const bool on  = (l < HH);

    const int gA = grp ? 2 : 0;          // f or g
    const int gB = grp ? 3 : 1;          // i or o

    float wA[HH], wB[HH];
#pragma unroll
    for (int j = 0; j < HH; j++) {
        wA[j] = on ? Wg[gA * WG_STRIDE + (EE + j) * HH + l] : 0.f;
        wB[j] = on ? Wg[gB * WG_STRIDE + (EE + j) * HH + l] : 0.f;
    }

    // gate A activation: grp0 sigmoid -> 0.5 + 0.5*tanh(0.5x); grp1 tanh
    const float ssA = grp ? 1.f : 0.5f;
    const float kA  = grp ? 1.f : 0.5f;
    const float bAc = grp ? 0.f : 0.5f;

    float hx = 0.f, cx = 0.f;
    const float* bpA = g_base + (size_t)b * NG + gA * 10 + l;
    const float* bpB = g_base + (size_t)b * NG + gB * 10 + l;
    const size_t tstride = (size_t)SN * NG;

    int safe = -1;   // highest t whose g_base rows are known complete
#define ENSURE(tmax_) do { int _t = (tmax_); if (_t > safe) { \
        int _q = _t >> 6; \
        volatile int* _qc = g_qcnt + _q; \
        while (*_qc < TILES_PER_Q) { } \
        __threadfence(); \
        safe = ((_q + 1) << 6) - 1; } } while (0)

    ENSURE(3);
    float pA[4], pB[4];
#pragma unroll
    for (int i = 0; i < 4; i++) {
        pA[i] = on ? bpA[i * tstride] : 0.f;
        pB[i] = on ? bpB[i * tstride] : 0.f;
    }

#pragma unroll 1
    for (int t0 = 0; t0 < SN; t0 += 4) {
        float nA[4], nB[4];
        if (t0 + 4 < SN) {
            ENSURE(t0 + 7 < SN ? t0 + 7 : SN - 1);
#pragma unroll
            for (int i = 0; i < 4; i++) {       // batch 8 LDGs -> MLP 8
                nA[i] = on ? bpA[(t0 + 4 + i) * tstride] : 0.f;
                nB[i] = on ? bpB[(t0 + 4 + i) * tstride] : 0.f;
            }
        } else {
#pragma unroll
            for (int i = 0; i < 4; i++) { nA[i] = 0.f; nB[i] = 0.f; }
        }
#pragma unroll
        for (int tt = 0; tt < 4; tt++) {
            // broadcast hx(t-1); split dot into two parallel chains
            float aA0 = pA[tt], aA1 = 0.f, aB0 = pB[tt], aB1 = 0.f;
#pragma unroll
            for (int j = 0; j < HH; j += 2) {
                float hj0 = __shfl_sync(0xffffffffu, hx, j, 16);
                float hj1 = __shfl_sync(0xffffffffu, hx, j + 1, 16);
                aA0 = fmaf(hj0, wA[j], aA0);
                aA1 = fmaf(hj1, wA[j + 1], aA1);
                aB0 = fmaf(hj0, wB[j], aB0);
                aB1 = fmaf(hj1, wB[j + 1], aB1);
            }
            float aA = aA0 + aA1, aB = aB0 + aB1;

            // qlayer: dual-register serial width-16 scan
            float cA = __cosf(aA), cB = __cosf(aB);
            float dA = (l == 0) ? 1.f : cA;
            float dB = (l == 0) ? 1.f : cB;
#pragma unroll
            for (int off = 1; off < 16; off <<= 1) {
                float vA = __shfl_up_sync(0xffffffffu, dA, off, 16);
                float vB = __shfl_up_sync(0xffffffffu, dB, off, 16);
                if (l >= off) { dA *= vA; dB *= vB; }
            }
            float c0A = __shfl_sync(0xffffffffu, cA, 0, 16);
            float c0B = __shfl_sync(0xffffffffu, cB, 0, 16);
            float q9A = __shfl_sync(0xffffffffu, dA, HH - 1, 16);
            float q9B = __shfl_sync(0xffffffffu, dB, HH - 1, 16);
            float qA = (l == 0) ? q9A : c0A * dA;
            float qB = (l == 0) ? q9B : c0B * dB;

            // activations via tanh.approx
            float actA = fmaf(kA, tanhapx(ssA * qA), bAc);          // f / g
            float actB = fmaf(0.5f, tanhapx(0.5f * qB), 0.5f);      // i / o

            // exchange halves: grp0 gets (g,o), grp1 gets (f,i)
            float xA = __shfl_xor_sync(0xffffffffu, actA, 16);
            float xB = __shfl_xor_sync(0xffffffffu, actB, 16);
            float f  = grp ? xA   : actA;
            float ii = grp ? xB   : actB;
            float gg = grp ? actA : xA;
            float o  = grp ? actB : xB;

            cx = fmaf(f, cx, ii * gg);
            hx = o * tanhapx(cx);

            if (on && grp == 0) g_hx[((size_t)(t0 + tt) * SN + b) * HH + l] = hx;
        }
#pragma unroll
        for (int i = 0; i < 4; i++) { pA[i] = nA[i]; pB[i] = nB[i]; }
    }
#undef ENSURE
}

// =========================================================================
// Phase C: logits = hx @ W_out + b_out, then log_softmax over T=50.
// One row per thread; output staged in 16B-aligned smem, then
// block-cooperative float4 copy (coalesced stores).
// =========================================================================
__global__ __launch_bounds__(128) void phaseC_kernel(
    const float* __restrict__ Wout, const float* __restrict__ bout,
    float* __restrict__ out)
{
    __shared__ __align__(16) float sOut[128 * TT];   // 25.6 KB, 16B aligned
    __shared__ float sW[HH * TT];
    __shared__ float sbv[TT];
    const int tid = threadIdx.x;
    for (int i = tid; i < HH * TT; i += 128) sW[i] = Wout[i];
    for (int i = tid; i < TT;      i += 128) sbv[i] = bout[i];
    __syncthreads();

    const int row = blockIdx.x * 128 + tid;
    float h[HH];
#pragma unroll
    for (int j = 0; j < HH; j += 2) {
        float2 v = *(const float2*)(g_hx + (size_t)row * HH + j);
        h[j] = v.x; h[j + 1] = v.y;
    }

    float lg[TT];
#pragma unroll
    for (int c = 0; c < TT; c++) {
        float s = sbv[c];
#pragma unroll
        for (int j = 0; j < HH; j++) s = fmaf(h[j], sW[j * TT + c], s);
        lg[c] = s;
    }
    float m = lg[0];
#pragma unroll
    for (int c = 1; c < TT; c++) m = fmaxf(m, lg[c]);
    float sum = 0.f;
#pragma unroll
    for (int c = 0; c < TT; c++) sum += __expf(lg[c] - m);
    float ls = m + __logf(sum);

    float2* sp = (float2*)(sOut + tid * TT);
#pragma unroll
    for (int c = 0; c < TT / 2; c++)
        sp[c] = make_float2(lg[2 * c] - ls, lg[2 * c + 1] - ls);
    __syncthreads();

    // coalesced block copy: 128*50 floats = 1600 float4
    const float4* src = (const float4*)sOut;
    float4* dst = (float4*)(out + (size_t)blockIdx.x * 128 * TT);
#pragma unroll
    for (int i = 0; i < 13; i++) {
        int idx = i * 128 + tid;
        if (idx < (128 * TT) / 4) dst[idx] = src[idx];
    }
}

// =========================================================================
extern "C" void kernel_launch(void* const* d_in, const int* in_sizes, int n_in,
                              void* d_out, int out_size)
{
    const int*   tok   = (const int*)d_in[0];     // sentence (256,256) int32
    const float* emb   = (const float*)d_in[1];   // (V, E)
    const float* Wg    = (const float*)d_in[2];   // (4, E+H, H)
    const float* bg    = (const float*)d_in[3];   // (4, H)
    const float* theta = (const float*)d_in[4];   // (4, H)
    const float* Wout  = (const float*)d_in[5];   // (H, T)
    const float* bout  = (const float*)d_in[6];   // (T)
    float* out = (float*)d_out;                   // (256,256,50) float32

    cudaFuncSetAttribute(phaseAB_kernel, cudaFuncAttributeMaxDynamicSharedMemorySize, SM_TOT);

    zeroQ_kernel<<<1, 32>>>();
    prepB_kernel<<<(NCH * NG * BK + 255) / 256, 256>>>(Wg);
    phaseAB_kernel<<<NA_BLK + SN, 128, SM_TOT>>>(tok, emb, bg, theta, Wg);
    phaseC_kernel<<<NP / 128, 128>>>(Wout, bout, out);
}

// round 14
// speedup vs baseline: 1.1967x; 1.1967x over previous
#include <cuda_runtime.h>
#include <cstdint>

// Problem constants
#define SN 256        // batch == seq_len
#define EE 1024       // embedding dim
#define HH 10         // hidden dim
#define NG 40         // 4 gates * H
#define TT 50         // tagset size
#define NP (SN*SN)    // 65536 rows (t,b)
#define WG_STRIDE 10340  // (E+H)*H per gate

// Phase A tiling (mma.sync m16n8k8 tf32)
#define BK 32         // k chunk
#define MT 128        // rows per block
#define ATHREADS 128  // 4 warps: each 2 m-tiles x 5 n-tiles
#define NCH (EE/BK)   // 32 chunks
#define AST 36        // padded row stride (floats) -> conflict-free fragment loads
#define A_STAGE_F (MT*AST)   // 4608 floats
#define B_STAGE_F (NG*AST)   // 1440 floats

// smem layout (bytes)
#define SM_STOK 0
#define SM_A    1024
#define SM_B    (SM_A + 2*A_STAGE_F*4)      // 37888
#define SM_TOT  (SM_B + 2*B_STAGE_F*4)      // 49408

// Scratch (no allocations allowed -> device globals)
__device__ float g_base[(size_t)NP * NG];   // x@Wx + bg + theta
__device__ float g_hx[(size_t)NP * HH];     // hx outputs of the scan
__device__ __align__(16) float g_Bt[NCH * NG * BK];  // B transposed per chunk, tf32-rounded

// ---------- helpers ----------
__device__ __forceinline__ void cp16(uint32_t dst, const void* src) {
    asm volatile("cp.async.cg.shared.global [%0], [%1], 16;" :: "r"(dst), "l"(src) : "memory");
}
__device__ __forceinline__ void hmma_tf32(float* d, uint32_t a0, uint32_t a1, uint32_t a2, uint32_t a3,
                                          uint32_t b0, uint32_t b1) {
    asm volatile(
        "mma.sync.aligned.m16n8k8.row.col.f32.tf32.tf32.f32 "
        "{%0,%1,%2,%3}, {%4,%5,%6,%7}, {%8,%9}, {%0,%1,%2,%3};"
        : "+f"(d[0]), "+f"(d[1]), "+f"(d[2]), "+f"(d[3])
        : "r"(a0), "r"(a1), "r"(a2), "r"(a3), "r"(b0), "r"(b1));
}
__device__ __forceinline__ float tanhapx(float x) {
    float y;
    asm("tanh.approx.f32 %0, %1;" : "=f"(y) : "f"(x));
    return y;
}

// =========================================================================
// B pre-transpose + tf32 round: g_Bt[ch][n][k]
// =========================================================================
__global__ __launch_bounds__(256) void prepB_kernel(const float* __restrict__ Wg)
{
    int idx = blockIdx.x * 256 + threadIdx.x;          // 0..40959
    if (idx >= NCH * NG * BK) return;
    int ch = idx / (NG * BK);
    int r  = idx % (NG * BK);
    int n  = r / BK, k = r % BK;
    float v = Wg[(n / HH) * WG_STRIDE + (ch * BK + k) * HH + (n % HH)];
    uint32_t u;
    asm("cvt.rna.tf32.f32 %0, %1;" : "=r"(u) : "f"(v));
    g_Bt[idx] = __uint_as_float(u);
}

// =========================================================================
// Phase A: gathered skinny GEMM on mma.sync tf32 (HMMA).
// 128 rows x 40 cols per CTA. A: k-major smem, stride 36 floats (conflict-
// free fragment loads). B: [n][k] stride 36. Double-buffered cp.async.
// =========================================================================
extern __shared__ char smem_raw[];

__global__ __launch_bounds__(ATHREADS, 4) void phaseA_kernel(
    const int* __restrict__ tok, const float* __restrict__ emb,
    const float* __restrict__ bg, const float* __restrict__ theta)
{
    int*   stok = (int*)(smem_raw + SM_STOK);
    float* sA   = (float*)(smem_raw + SM_A);
    float* sB   = (float*)(smem_raw + SM_B);

    const int tid = threadIdx.x;
    const int rowbase = blockIdx.x * MT;

    if (tid < MT) stok[tid] = tok[rowbase + tid];
    __syncthreads();

    const int wid  = tid >> 5, lane = tid & 31;
    const int g    = lane >> 2, t = lane & 3;
    const int w32  = wid * 32;

    float acc[2][5][4];
#pragma unroll
    for (int m = 0; m < 2; m++)
#pragma unroll
        for (int n = 0; n < 5; n++)
#pragma unroll
            for (int q = 0; q < 4; q++) acc[m][n][q] = 0.f;

    const uint32_t sA_base = (uint32_t)__cvta_generic_to_shared(sA);
    const uint32_t sB_base = (uint32_t)__cvta_generic_to_shared(sB);

    auto issue_chunk = [&](int ch) {
        const int s = ch & 1;
        const uint32_t abase = sA_base + (uint32_t)(s * A_STAGE_F * 4);
#pragma unroll
        for (int it = 0; it < 8; it++) {
            int idx = it * ATHREADS + tid;
            int row = idx >> 3, c = idx & 7;
            cp16(abase + (uint32_t)(row * (AST * 4) + (c << 4)),
                 emb + (size_t)stok[row] * EE + ch * BK + (c << 2));
        }
        const uint32_t bbase = sB_base + (uint32_t)(s * B_STAGE_F * 4);
        const float* bsrc = g_Bt + ch * (NG * BK);
#pragma unroll
        for (int it = 0; it < 3; it++) {
            int i = it * ATHREADS + tid;
            if (i < NG * 8) {
                int n = i >> 3, kq = i & 7;
                cp16(bbase + (uint32_t)(n * (AST * 4) + (kq << 4)), bsrc + (i << 2));
            }
        }
        asm volatile("cp.async.commit_group;" ::: "memory");
    };

    issue_chunk(0);

    for (int ch = 0; ch < NCH; ch++) {
        asm volatile("cp.async.wait_group 0;" ::: "memory");
        __syncthreads();
        if (ch + 1 < NCH) issue_chunk(ch + 1);

        const int s = ch & 1;
        const uint32_t* A = (const uint32_t*)(sA + s * A_STAGE_F);
        const uint32_t* B = (const uint32_t*)(sB + s * B_STAGE_F);
#pragma unroll
        for (int s4 = 0; s4 < 4; s4++) {
            uint32_t b0[5], b1[5];
#pragma unroll
            for (int n = 0; n < 5; n++) {
                const uint32_t* bp = B + (n * 8 + g) * AST + s4 * 8 + t;
                b0[n] = bp[0];
                b1[n] = bp[4];
            }
#pragma unroll
            for (int m = 0; m < 2; m++) {
                const uint32_t* ap = A + (w32 + m * 16 + g) * AST + s4 * 8 + t;
                uint32_t a0 = ap[0];
                uint32_t a2 = ap[4];
                uint32_t a1 = ap[8 * AST];
                uint32_t a3 = ap[8 * AST + 4];
#pragma unroll
                for (int n = 0; n < 5; n++)
                    hmma_tf32(acc[m][n], a0, a1, a2, a3, b0[n], b1[n]);
            }
        }
    }

    // epilogue: add bg + theta, store (D frag: rows g/g+8, cols 2t,2t+1)
    float cbx[5], cby[5];
#pragma unroll
    for (int n = 0; n < 5; n++) {
        int col = n * 8 + 2 * t;
        cbx[n] = bg[col] + theta[col];
        cby[n] = bg[col + 1] + theta[col + 1];
    }
#pragma unroll
    for (int m = 0; m < 2; m++) {
        int row0 = rowbase + w32 + m * 16 + g;
#pragma unroll
        for (int n = 0; n < 5; n++) {
            int col = n * 8 + 2 * t;
            *(float2*)(g_base + (size_t)row0 * NG + col) =
                make_float2(acc[m][n][0] + cbx[n], acc[m][n][1] + cby[n]);
            *(float2*)(g_base + (size_t)(row0 + 8) * NG + col) =
                make_float2(acc[m][n][2] + cbx[n], acc[m][n][3] + cby[n]);
        }
    }
}

// =========================================================================
// Phase B: one LSTM chain per warp (best measured structure).
// Lanes 0-15: gates (f,i); lanes 16-31: gates (g,o); hx/cx replicated.
// Activations via tanh.approx (sigmoid = 0.5 + 0.5*tanh(x/2)).
// Runs alone on the chip — its per-step critical path is the wall time.
// =========================================================================
__global__ __launch_bounds__(32) void phaseB_kernel(const float* __restrict__ Wg)
{
    const int lane = threadIdx.x;
    const int grp  = lane >> 4;          // 0: f,i   1: g,o
    const int l    = lane & 15;
    const int b    = blockIdx.x;
    const bool on  = (l < HH);

    const int gA = grp ? 2 : 0;          // f or g
    const int gB = grp ? 3 : 1;          // i or o

    float wA[HH], wB[HH];
#pragma unroll
    for (int j = 0; j < HH; j++) {
        wA[j] = on ? Wg[gA * WG_STRIDE + (EE + j) * HH + l] : 0.f;
        wB[j] = on ? Wg[gB * WG_STRIDE + (EE + j) * HH + l] : 0.f;
    }

    // gate A activation: grp0 sigmoid -> 0.5 + 0.5*tanh(0.5x); grp1 tanh
    const float ssA = grp ? 1.f : 0.5f;
    const float kA  = grp ? 1.f : 0.5f;
    const float bAc = grp ? 0.f : 0.5f;

    float hx = 0.f, cx = 0.f;
    const float* bpA = g_base + (size_t)b * NG + gA * 10 + l;
    const float* bpB = g_base + (size_t)b * NG + gB * 10 + l;
    const size_t tstride = (size_t)SN * NG;

    float pA[4], pB[4];
#pragma unroll
    for (int i = 0; i < 4; i++) {
        pA[i] = on ? bpA[i * tstride] : 0.f;
        pB[i] = on ? bpB[i * tstride] : 0.f;
    }

#pragma unroll 1
    for (int t0 = 0; t0 < SN; t0 += 4) {
        float nA[4], nB[4];
        if (t0 + 4 < SN) {
#pragma unroll
            for (int i = 0; i < 4; i++) {       // batch 8 LDGs -> MLP 8
                nA[i] = on ? bpA[(t0 + 4 + i) * tstride] : 0.f;
                nB[i] = on ? bpB[(t0 + 4 + i) * tstride] : 0.f;
            }
        } else {
#pragma unroll
            for (int i = 0; i < 4; i++) { nA[i] = 0.f; nB[i] = 0.f; }
        }
#pragma unroll
        for (int tt = 0; tt < 4; tt++) {
            // broadcast hx(t-1); split dot into two parallel chains
            float aA0 = pA[tt], aA1 = 0.f, aB0 = pB[tt], aB1 = 0.f;
#pragma unroll
            for (int j = 0; j < HH; j += 2) {
                float hj0 = __shfl_sync(0xffffffffu, hx, j, 16);
                float hj1 = __shfl_sync(0xffffffffu, hx, j + 1, 16);
                aA0 = fmaf(hj0, wA[j], aA0);
                aA1 = fmaf(hj1, wA[j + 1], aA1);
                aB0 = fmaf(hj0, wB[j], aB0);
                aB1 = fmaf(hj1, wB[j + 1], aB1);
            }
            float aA = aA0 + aA1, aB = aB0 + aB1;

            // qlayer: dual-register serial width-16 scan
            float cA = __cosf(aA), cB = __cosf(aB);
            float dA = (l == 0) ? 1.f : cA;
            float dB = (l == 0) ? 1.f : cB;
#pragma unroll
            for (int off = 1; off < 16; off <<= 1) {
                float vA = __shfl_up_sync(0xffffffffu, dA, off, 16);
                float vB = __shfl_up_sync(0xffffffffu, dB, off, 16);
                if (l >= off) { dA *= vA; dB *= vB; }
            }
            float c0A = __shfl_sync(0xffffffffu, cA, 0, 16);
            float c0B = __shfl_sync(0xffffffffu, cB, 0, 16);
            float q9A = __shfl_sync(0xffffffffu, dA, HH - 1, 16);
            float q9B = __shfl_sync(0xffffffffu, dB, HH - 1, 16);
            float qA = (l == 0) ? q9A : c0A * dA;
            float qB = (l == 0) ? q9B : c0B * dB;

            // activations via tanh.approx
            float actA = fmaf(kA, tanhapx(ssA * qA), bAc);          // f / g
            float actB = fmaf(0.5f, tanhapx(0.5f * qB), 0.5f);      // i / o

            // exchange halves: grp0 gets (g,o), grp1 gets (f,i)
            float xA = __shfl_xor_sync(0xffffffffu, actA, 16);
            float xB = __shfl_xor_sync(0xffffffffu, actB, 16);
            float f  = grp ? xA   : actA;
            float ii = grp ? xB   : actB;
            float gg = grp ? actA : xA;
            float o  = grp ? actB : xB;

            cx = fmaf(f, cx, ii * gg);
            hx = o * tanhapx(cx);

            if (on && grp == 0) g_hx[((size_t)(t0 + tt) * SN + b) * HH + l] = hx;
        }
#pragma unroll
        for (int i = 0; i < 4; i++) { pA[i] = nA[i]; pB[i] = nB[i]; }
    }
}

// =========================================================================
// Phase C: logits = hx @ W_out + b_out, then log_softmax over T=50.
// One row per thread; output staged in 16B-aligned smem, then
// block-cooperative float4 copy (coalesced stores). Measured 10.7us.
// =========================================================================
__global__ __launch_bounds__(128) void phaseC_kernel(
    const float* __restrict__ Wout, const float* __restrict__ bout,
    float* __restrict__ out)
{
    __shared__ __align__(16) float sOut[128 * TT];   // 25.6 KB, 16B aligned
    __shared__ float sW[HH * TT];
    __shared__ float sbv[TT];
    const int tid = threadIdx.x;
    for (int i = tid; i < HH * TT; i += 128) sW[i] = Wout[i];
    for (int i = tid; i < TT;      i += 128) sbv[i] = bout[i];
    __syncthreads();

    const int row = blockIdx.x * 128 + tid;
    float h[HH];
#pragma unroll
    for (int j = 0; j < HH; j += 2) {
        float2 v = *(const float2*)(g_hx + (size_t)row * HH + j);
        h[j] = v.x; h[j + 1] = v.y;
    }

    float lg[TT];
#pragma unroll
    for (int c = 0; c < TT; c++) {
        float s = sbv[c];
#pragma unroll
        for (int j = 0; j < HH; j++) s = fmaf(h[j], sW[j * TT + c], s);
        lg[c] = s;
    }
    float m = lg[0];
#pragma unroll
    for (int c = 1; c < TT; c++) m = fmaxf(m, lg[c]);
    float sum = 0.f;
#pragma unroll
    for (int c = 0; c < TT; c++) sum += __expf(lg[c] - m);
    float ls = m + __logf(sum);

    float2* sp = (float2*)(sOut + tid * TT);
#pragma unroll
    for (int c = 0; c < TT / 2; c++)
        sp[c] = make_float2(lg[2 * c] - ls, lg[2 * c + 1] - ls);
    __syncthreads();

    // coalesced block copy: 128*50 floats = 1600 float4
    const float4* src = (const float4*)sOut;
    float4* dst = (float4*)(out + (size_t)blockIdx.x * 128 * TT);
#pragma unroll
    for (int i = 0; i < 13; i++) {
        int idx = i * 128 + tid;
        if (idx < (128 * TT) / 4) dst[idx] = src[idx];
    }
}

// =========================================================================
extern "C" void kernel_launch(void* const* d_in, const int* in_sizes, int n_in,
                              void* d_out, int out_size)
{
    const int*   tok   = (const int*)d_in[0];     // sentence (256,256) int32
    const float* emb   = (const float*)d_in[1];   // (V, E)
    const float* Wg    = (const float*)d_in[2];   // (4, E+H, H)
    const float* bg    = (const float*)d_in[3];   // (4, H)
    const float* theta = (const float*)d_in[4];   // (4, H)
    const float* Wout  = (const float*)d_in[5];   // (H, T)
    const float* bout  = (const float*)d_in[6];   // (T)
    float* out = (float*)d_out;                   // (256,256,50) float32

    cudaFuncSetAttribute(phaseA_kernel, cudaFuncAttributeMaxDynamicSharedMemorySize, SM_TOT);

    prepB_kernel<<<(NCH * NG * BK + 255) / 256, 256>>>(Wg);
    phaseA_kernel<<<NP / MT, ATHREADS, SM_TOT>>>(tok, emb, bg, theta);
    phaseB_kernel<<<SN, 32>>>(Wg);
    phaseC_kernel<<<NP / 128, 128>>>(Wout, bout, out);
}

// round 16
// speedup vs baseline: 1.2381x; 1.0346x over previous
#include <cuda_runtime.h>
#include <cstdint>

// Problem constants
#define SN 256        // batch == seq_len
#define EE 1024       // embedding dim
#define HH 10         // hidden dim
#define NG 40         // 4 gates * H
#define TT 50         // tagset size
#define NP (SN*SN)    // 65536 rows (t,b)
#define WG_STRIDE 10340  // (E+H)*H per gate

// Phase A tiling (mma.sync m16n8k8 tf32)
#define BK 32         // k chunk
#define MT 128        // rows per block
#define ATHREADS 128  // 4 warps: each 2 m-tiles x 5 n-tiles
#define NCH (EE/BK)   // 32 chunks
#define AST 36        // padded row stride (floats) -> conflict-free fragment loads
#define A_STAGE_F (MT*AST)   // 4608 floats
#define B_STAGE_F (NG*AST)   // 1440 floats

// smem layout (bytes)
#define SM_STOK 0
#define SM_A    1024
#define SM_B    (SM_A + 2*A_STAGE_F*4)      // 37888
#define SM_TOT  (SM_B + 2*B_STAGE_F*4)      // 49408

// Scratch (no allocations allowed -> device globals)
__device__ float g_base[(size_t)NP * NG];   // x@Wx + bg + theta
__device__ float g_hx[(size_t)NP * HH];     // hx outputs of the scan
__device__ __align__(16) float g_Bt[NCH * NG * BK];  // B transposed per chunk, tf32-rounded

// ---------- helpers ----------
__device__ __forceinline__ void cp16(uint32_t dst, const void* src) {
    asm volatile("cp.async.cg.shared.global [%0], [%1], 16;" :: "r"(dst), "l"(src) : "memory");
}
__device__ __forceinline__ void hmma_tf32(float* d, uint32_t a0, uint32_t a1, uint32_t a2, uint32_t a3,
                                          uint32_t b0, uint32_t b1) {
    asm volatile(
        "mma.sync.aligned.m16n8k8.row.col.f32.tf32.tf32.f32 "
        "{%0,%1,%2,%3}, {%4,%5,%6,%7}, {%8,%9}, {%0,%1,%2,%3};"
        : "+f"(d[0]), "+f"(d[1]), "+f"(d[2]), "+f"(d[3])
        : "r"(a0), "r"(a1), "r"(a2), "r"(a3), "r"(b0), "r"(b1));
}
__device__ __forceinline__ float tanhapx(float x) {
    float y;
    asm("tanh.approx.f32 %0, %1;" : "=f"(y) : "f"(x));
    return y;
}

// =========================================================================
// B pre-transpose + tf32 round: g_Bt[ch][n][k]
// =========================================================================
__global__ __launch_bounds__(256) void prepB_kernel(const float* __restrict__ Wg)
{
    int idx = blockIdx.x * 256 + threadIdx.x;          // 0..40959
    if (idx >= NCH * NG * BK) return;
    int ch = idx / (NG * BK);
    int r  = idx % (NG * BK);
    int n  = r / BK, k = r % BK;
    float v = Wg[(n / HH) * WG_STRIDE + (ch * BK + k) * HH + (n % HH)];
    uint32_t u;
    asm("cvt.rna.tf32.f32 %0, %1;" : "=r"(u) : "f"(v));
    g_Bt[idx] = __uint_as_float(u);
}

// =========================================================================
// Phase A: gathered skinny GEMM on mma.sync tf32 (HMMA).
// 128 rows x 40 cols per CTA. A: k-major smem, stride 36 floats (conflict-
// free fragment loads). B: [n][k] stride 36. Double-buffered cp.async.
// =========================================================================
extern __shared__ char smem_raw[];

__global__ __launch_bounds__(ATHREADS, 4) void phaseA_kernel(
    const int* __restrict__ tok, const float* __restrict__ emb,
    const float* __restrict__ bg, const float* __restrict__ theta)
{
    int*   stok = (int*)(smem_raw + SM_STOK);
    float* sA   = (float*)(smem_raw + SM_A);
    float* sB   = (float*)(smem_raw + SM_B);

    const int tid = threadIdx.x;
    const int rowbase = blockIdx.x * MT;

    if (tid < MT) stok[tid] = tok[rowbase + tid];
    __syncthreads();

    const int wid  = tid >> 5, lane = tid & 31;
    const int g    = lane >> 2, t = lane & 3;
    const int w32  = wid * 32;

    float acc[2][5][4];
#pragma unroll
    for (int m = 0; m < 2; m++)
#pragma unroll
        for (int n = 0; n < 5; n++)
#pragma unroll
            for (int q = 0; q < 4; q++) acc[m][n][q] = 0.f;

    const uint32_t sA_base = (uint32_t)__cvta_generic_to_shared(sA);
    const uint32_t sB_base = (uint32_t)__cvta_generic_to_shared(sB);

    auto issue_chunk = [&](int ch) {
        const int s = ch & 1;
        const uint32_t abase = sA_base + (uint32_t)(s * A_STAGE_F * 4);
#pragma unroll
        for (int it = 0; it < 8; it++) {
            int idx = it * ATHREADS + tid;
            int row = idx >> 3, c = idx & 7;
            cp16(abase + (uint32_t)(row * (AST * 4) + (c << 4)),
                 emb + (size_t)stok[row] * EE + ch * BK + (c << 2));
        }
        const uint32_t bbase = sB_base + (uint32_t)(s * B_STAGE_F * 4);
        const float* bsrc = g_Bt + ch * (NG * BK);
#pragma unroll
        for (int it = 0; it < 3; it++) {
            int i = it * ATHREADS + tid;
            if (i < NG * 8) {
                int n = i >> 3, kq = i & 7;
                cp16(bbase + (uint32_t)(n * (AST * 4) + (kq << 4)), bsrc + (i << 2));
            }
        }
        asm volatile("cp.async.commit_group;" ::: "memory");
    };

    issue_chunk(0);

    for (int ch = 0; ch < NCH; ch++) {
        asm volatile("cp.async.wait_group 0;" ::: "memory");
        __syncthreads();
        if (ch + 1 < NCH) issue_chunk(ch + 1);

        const int s = ch & 1;
        const uint32_t* A = (const uint32_t*)(sA + s * A_STAGE_F);
        const uint32_t* B = (const uint32_t*)(sB + s * B_STAGE_F);
#pragma unroll
        for (int s4 = 0; s4 < 4; s4++) {
            uint32_t b0[5], b1[5];
#pragma unroll
            for (int n = 0; n < 5; n++) {
                const uint32_t* bp = B + (n * 8 + g) * AST + s4 * 8 + t;
                b0[n] = bp[0];
                b1[n] = bp[4];
            }
#pragma unroll
            for (int m = 0; m < 2; m++) {
                const uint32_t* ap = A + (w32 + m * 16 + g) * AST + s4 * 8 + t;
                uint32_t a0 = ap[0];
                uint32_t a2 = ap[4];
                uint32_t a1 = ap[8 * AST];
                uint32_t a3 = ap[8 * AST + 4];
#pragma unroll
                for (int n = 0; n < 5; n++)
                    hmma_tf32(acc[m][n], a0, a1, a2, a3, b0[n], b1[n]);
            }
        }
    }

    // epilogue: add bg + theta, store (D frag: rows g/g+8, cols 2t,2t+1)
    float cbx[5], cby[5];
#pragma unroll
    for (int n = 0; n < 5; n++) {
        int col = n * 8 + 2 * t;
        cbx[n] = bg[col] + theta[col];
        cby[n] = bg[col + 1] + theta[col + 1];
    }
#pragma unroll
    for (int m = 0; m < 2; m++) {
        int row0 = rowbase + w32 + m * 16 + g;
#pragma unroll
        for (int n = 0; n < 5; n++) {
            int col = n * 8 + 2 * t;
            *(float2*)(g_base + (size_t)row0 * NG + col) =
                make_float2(acc[m][n][0] + cbx[n], acc[m][n][1] + cby[n]);
            *(float2*)(g_base + (size_t)(row0 + 8) * NG + col) =
                make_float2(acc[m][n][2] + cbx[n], acc[m][n][3] + cby[n]);
        }
    }
}

// =========================================================================
// Phase B: one LSTM chain per warp. Lanes 0-15: gates (f,i); lanes 16-31:
// gates (g,o); hx/cx replicated. Rotated lane mapping: lane l handles wire
// w=(l+1)%10, so the inclusive radix-4 prefix scan (offsets {1,2,3} then
// {4,8,12} — 2 levels, ~76 cyc vs 120) directly yields:
//   lanes 0..8 (wires 1..9): q = c0bc * prefix      (c0bc = shfl(c,9), pre-scan)
//   lane  9    (wire 0)    : q = prefix * rcp(own c) (full product / c0)
// eliminating the post-scan q9 shuffle. Activations via tanh.approx.
// =========================================================================
__global__ __launch_bounds__(32) void phaseB_kernel(const float* __restrict__ Wg)
{
    const int lane = threadIdx.x;
    const int grp  = lane >> 4;          // 0: f,i   1: g,o
    const int l    = lane & 15;
    const int b    = blockIdx.x;
    const bool on  = (l < HH);
    const int  w   = (l + 1) % HH;       // rotated wire index

    const int gA = grp ? 2 : 0;          // f or g
    const int gB = grp ? 3 : 1;          // i or o

    float wA[HH], wB[HH];
#pragma unroll
    for (int j = 0; j < HH; j++) {
        wA[j] = on ? Wg[gA * WG_STRIDE + (EE + j) * HH + w] : 0.f;
        wB[j] = on ? Wg[gB * WG_STRIDE + (EE + j) * HH + w] : 0.f;
    }

    // gate A activation: grp0 sigmoid -> 0.5 + 0.5*tanh(0.5x); grp1 tanh
    const float ssA = grp ? 1.f : 0.5f;
    const float kA  = grp ? 1.f : 0.5f;
    const float bAc = grp ? 0.f : 0.5f;

    float hx = 0.f, cx = 0.f;
    const float* bpA = g_base + (size_t)b * NG + gA * 10 + w;
    const float* bpB = g_base + (size_t)b * NG + gB * 10 + w;
    const size_t tstride = (size_t)SN * NG;

    float pA[4], pB[4];
#pragma unroll
    for (int i = 0; i < 4; i++) {
        pA[i] = on ? bpA[i * tstride] : 0.f;
        pB[i] = on ? bpB[i * tstride] : 0.f;
    }

#pragma unroll 1
    for (int t0 = 0; t0 < SN; t0 += 4) {
        float nA[4], nB[4];
        if (t0 + 4 < SN) {
#pragma unroll
            for (int i = 0; i < 4; i++) {       // batch 8 LDGs -> MLP 8
                nA[i] = on ? bpA[(t0 + 4 + i) * tstride] : 0.f;
                nB[i] = on ? bpB[(t0 + 4 + i) * tstride] : 0.f;
            }
        } else {
#pragma unroll
            for (int i = 0; i < 4; i++) { nA[i] = 0.f; nB[i] = 0.f; }
        }
#pragma unroll
        for (int tt = 0; tt < 4; tt++) {
            // broadcast hx(t-1): wire j lives at lane (j+9)%10
            float aA0 = pA[tt], aA1 = 0.f, aB0 = pB[tt], aB1 = 0.f;
#pragma unroll
            for (int j = 0; j < HH; j += 2) {
                float hj0 = __shfl_sync(0xffffffffu, hx, (j + 9) % 10, 16);  // wire j
                float hj1 = __shfl_sync(0xffffffffu, hx, j, 16);             // wire j+1
                aA0 = fmaf(hj0, wA[j], aA0);
                aA1 = fmaf(hj1, wA[j + 1], aA1);
                aB0 = fmaf(hj0, wB[j], aB0);
                aB1 = fmaf(hj1, wB[j + 1], aB1);
            }
            float aA = aA0 + aA1, aB = aB0 + aB1;

            // qlayer: cos, then radix-4 inclusive prefix scan (2 levels)
            float cA = __cosf(aA), cB = __cosf(aB);
            float dA = cA, dB = cB;
            // pre-scan (off critical path): c0 broadcast + own reciprocal
            float c0A = __shfl_sync(0xffffffffu, cA, 9, 16);
            float c0B = __shfl_sync(0xffffffffu, cB, 9, 16);
            float rcA = __fdividef(1.f, cA);
            float rcB = __fdividef(1.f, cB);
            // level 1: offsets 1,2,3
            {
                float a1 = __shfl_up_sync(0xffffffffu, dA, 1, 16);
                float a2 = __shfl_up_sync(0xffffffffu, dA, 2, 16);
                float a3 = __shfl_up_sync(0xffffffffu, dA, 3, 16);
                float b1 = __shfl_up_sync(0xffffffffu, dB, 1, 16);
                float b2 = __shfl_up_sync(0xffffffffu, dB, 2, 16);
                float b3 = __shfl_up_sync(0xffffffffu, dB, 3, 16);
                float mA = ((l >= 1) ? a1 : 1.f) * ((l >= 2) ? a2 : 1.f);
                float mB = ((l >= 1) ? b1 : 1.f) * ((l >= 2) ? b2 : 1.f);
                dA *= mA * ((l >= 3) ? a3 : 1.f);
                dB *= mB * ((l >= 3) ? b3 : 1.f);
            }
            // level 2: offsets 4,8,12
            {
                float a1 = __shfl_up_sync(0xffffffffu, dA, 4, 16);
                float a2 = __shfl_up_sync(0xffffffffu, dA, 8, 16);
                float a3 = __shfl_up_sync(0xffffffffu, dA, 12, 16);
                float b1 = __shfl_up_sync(0xffffffffu, dB, 4, 16);
                float b2 = __shfl_up_sync(0xffffffffu, dB, 8, 16);
                float b3 = __shfl_up_sync(0xffffffffu, dB, 12, 16);
                float mA = ((l >= 4) ? a1 : 1.f) * ((l >= 8) ? a2 : 1.f);
                float mB = ((l >= 4) ? b1 : 1.f) * ((l >= 8) ? b2 : 1.f);
                dA *= mA * ((l >= 12) ? a3 : 1.f);
                dB *= mB * ((l >= 12) ? b3 : 1.f);
            }
            // finals: no post-scan shuffle
            float qA = dA * ((l == 9) ? rcA : c0A);
            float qB = dB * ((l == 9) ? rcB : c0B);

            // activations via tanh.approx
            float actA = fmaf(kA, tanhapx(ssA * qA), bAc);          // f / g
            float actB = fmaf(0.5f, tanhapx(0.5f * qB), 0.5f);      // i / o

            // exchange halves: grp0 gets (g,o), grp1 gets (f,i)
            float xA = __shfl_xor_sync(0xffffffffu, actA, 16);
            float xB = __shfl_xor_sync(0xffffffffu, actB, 16);
            float f  = grp ? xA   : actA;
            float ii = grp ? xB   : actB;
            float gg = grp ? actA : xA;
            float o  = grp ? actB : xB;

            cx = fmaf(f, cx, ii * gg);
            hx = o * tanhapx(cx);

            if (on && grp == 0) g_hx[((size_t)(t0 + tt) * SN + b) * HH + w] = hx;
        }
#pragma unroll
        for (int i = 0; i < 4; i++) { pA[i] = nA[i]; pB[i] = nB[i]; }
    }
}

// =========================================================================
// Phase C: logits = hx @ W_out + b_out, then log_softmax over T=50.
// One row per thread; output staged in 16B-aligned smem, then
// block-cooperative float4 copy (coalesced stores). Measured 10.7us.
// =========================================================================
__global__ __launch_bounds__(128) void phaseC_kernel(
    const float* __restrict__ Wout, const float* __restrict__ bout,
    float* __restrict__ out)
{
    __shared__ __align__(16) float sOut[128 * TT];   // 25.6 KB, 16B aligned
    __shared__ float sW[HH * TT];
    __shared__ float sbv[TT];
    const int tid = threadIdx.x;
    for (int i = tid; i < HH * TT; i += 128) sW[i] = Wout[i];
    for (int i = tid; i < TT;      i += 128) sbv[i] = bout[i];
    __syncthreads();

    const int row = blockIdx.x * 128 + tid;
    float h[HH];
#pragma unroll
    for (int j = 0; j < HH; j += 2) {
        float2 v = *(const float2*)(g_hx + (size_t)row * HH + j);
        h[j] = v.x; h[j + 1] = v.y;
    }

    float lg[TT];
#pragma unroll
    for (int c = 0; c < TT; c++) {
        float s = sbv[c];
#pragma unroll
        for (int j = 0; j < HH; j++) s = fmaf(h[j], sW[j * TT + c], s);
        lg[c] = s;
    }
    float m = lg[0];
#pragma unroll
    for (int c = 1; c < TT; c++) m = fmaxf(m, lg[c]);
    float sum = 0.f;
#pragma unroll
    for (int c = 0; c < TT; c++) sum += __expf(lg[c] - m);
    float ls = m + __logf(sum);

    float2* sp = (float2*)(sOut + tid * TT);
#pragma unroll
    for (int c = 0; c < TT / 2; c++)
        sp[c] = make_float2(lg[2 * c] - ls, lg[2 * c + 1] - ls);
    __syncthreads();

    // coalesced block copy: 128*50 floats = 1600 float4
    const float4* src = (const float4*)sOut;
    float4* dst = (float4*)(out + (size_t)blockIdx.x * 128 * TT);
#pragma unroll
    for (int i = 0; i < 13; i++) {
        int idx = i * 128 + tid;
        if (idx < (128 * TT) / 4) dst[idx] = src[idx];
    }
}

// =========================================================================
extern "C" void kernel_launch(void* const* d_in, const int* in_sizes, int n_in,
                              void* d_out, int out_size)
{
    const int*   tok   = (const int*)d_in[0];     // sentence (256,256) int32
    const float* emb   = (const float*)d_in[1];   // (V, E)
    const float* Wg    = (const float*)d_in[2];   // (4, E+H, H)
    const float* bg    = (const float*)d_in[3];   // (4, H)
    const float* theta = (const float*)d_in[4];   // (4, H)
    const float* Wout  = (const float*)d_in[5];   // (H, T)
    const float* bout  = (const float*)d_in[6];   // (T)
    float* out = (float*)d_out;                   // (256,256,50) float32

    cudaFuncSetAttribute(phaseA_kernel, cudaFuncAttributeMaxDynamicSharedMemorySize, SM_TOT);

    prepB_kernel<<<(NCH * NG * BK + 255) / 256, 256>>>(Wg);
    phaseA_kernel<<<NP / MT, ATHREADS, SM_TOT>>>(tok, emb, bg, theta);
    phaseB_kernel<<<SN, 32>>>(Wg);
    phaseC_kernel<<<NP / 128, 128>>>(Wout, bout, out);
}